// round 11
// baseline (speedup 1.0000x reference)
#include <cuda_runtime.h>
#include <cstdint>
#include <mma.h>

using namespace nvcuda;

#define BB 8192
#define DD 1024
#define EE 8
#define HH 4096
#define RROWS (BB * 2)
#define RPAD  17408              // 16384 + 8*128 pad
#define MTILES 136               // RPAD / 128

#define BM 128
#define BN 256
#define BK 32
#define NT 512                   // threads (16 warps, 4x4 grid, 32x64 each)
#define ASTR 36                  // A stride (floats): 32 + 4 pad
#define BSTR 264                 // B stride (floats): 256 + 8 pad
#define ASZ (BM * ASTR)          // 4608 floats
#define BSZ (BK * BSTR)          // 8448 floats
#define STG (ASZ + BSZ)          // 13056 floats / stage
#define SMEMSZ (2 * STG * 4)     // 104448 bytes

// ---------------- device scratch ----------------
__device__ int   g_tok_e[RROWS];
__device__ float g_tok_w[RROWS];
__device__ int   g_tok_pos[RROWS];
__device__ int   g_counts[EE];
__device__ int   g_poff[EE + 1];
__device__ int   g_row_token[RPAD];
__device__ int   g_tile_expert[MTILES];
__device__ float g_h[(size_t)RPAD * HH];
__device__ float g_y[(size_t)RPAD * DD];

typedef wmma::fragment<wmma::matrix_a, 16, 16, 8, wmma::precision::tf32, wmma::row_major> FragA;
typedef wmma::fragment<wmma::matrix_b, 16, 16, 8, wmma::precision::tf32, wmma::row_major> FragB;
typedef wmma::fragment<wmma::accumulator, 16, 16, 8, float> FragC;

__device__ __forceinline__ uint32_t smem_u32(const void* p) {
    uint32_t a;
    asm("{ .reg .u64 t; cvta.to.shared.u64 t, %1; cvt.u32.u64 %0, t; }" : "=r"(a) : "l"(p));
    return a;
}
__device__ __forceinline__ void cpa16(uint32_t dst, const void* src, uint32_t sz) {
    asm volatile("cp.async.cg.shared.global [%0], [%1], 16, %2;" :: "r"(dst), "l"(src), "r"(sz));
}
#define CPA_COMMIT() asm volatile("cp.async.commit_group;")
#define CPA_WAIT1()  asm volatile("cp.async.wait_group 1;")
#define CPA_WAIT0()  asm volatile("cp.async.wait_group 0;")

// ---------------------------------------------------------------------------
__global__ void init_kernel() {
    int idx = blockIdx.x * blockDim.x + threadIdx.x;
    if (idx < RPAD) g_row_token[idx] = -1;
    if (idx < EE)   g_counts[idx] = 0;
}

// ---------------------------------------------------------------------------
__global__ __launch_bounds__(256) void gate_kernel(const float* __restrict__ z,
                                                   const float* __restrict__ Wg,
                                                   const float* __restrict__ bg) {
    __shared__ float sWgT[EE * DD];
    int tid = threadIdx.x;
    for (int i = tid; i < DD * EE; i += 256) {
        int d = i >> 3, e = i & 7;
        sWgT[e * DD + d] = Wg[i];
    }
    __syncthreads();
    int warp = tid >> 5, lane = tid & 31;
    int t = blockIdx.x * 8 + warp;
    const float* zrow = z + (size_t)t * DD;
    float acc[EE];
#pragma unroll
    for (int e = 0; e < EE; e++) acc[e] = 0.0f;
    for (int d = lane; d < DD; d += 32) {
        float zv = zrow[d];
#pragma unroll
        for (int e = 0; e < EE; e++) acc[e] += zv * sWgT[e * DD + d];
    }
#pragma unroll
    for (int e = 0; e < EE; e++)
#pragma unroll
        for (int off = 16; off; off >>= 1)
            acc[e] += __shfl_xor_sync(0xffffffffu, acc[e], off);
    if (lane == 0) {
        float l[EE], m = -1e30f;
#pragma unroll
        for (int e = 0; e < EE; e++) { l[e] = acc[e] + bg[e]; m = fmaxf(m, l[e]); }
        float p[EE], Z = 0.0f;
#pragma unroll
        for (int e = 0; e < EE; e++) { p[e] = expf(l[e] - m); Z += p[e]; }
        float b1v = -1.0f, b2v = -1.0f; int i1 = 0, i2 = 0;
#pragma unroll
        for (int e = 0; e < EE; e++) {
            if (p[e] > b1v)      { b2v = b1v; i2 = i1; b1v = p[e]; i1 = e; }
            else if (p[e] > b2v) { b2v = p[e]; i2 = e; }
        }
        float invZ = 1.0f / Z;
        g_tok_e[t * 2 + 0] = i1;  g_tok_w[t * 2 + 0] = b1v * invZ;
        g_tok_e[t * 2 + 1] = i2;  g_tok_w[t * 2 + 1] = b2v * invZ;
        atomicAdd(&g_counts[i1], 1);
        atomicAdd(&g_counts[i2], 1);
    }
}

// fused offsets + tile-expert + scatter (single block)
__global__ void route_kernel() {
    __shared__ int s_poff[EE + 1];
    __shared__ int s_cur[EE];
    int tid = threadIdx.x;
    if (tid == 0) {
        int acc = 0;
        for (int e = 0; e < EE; e++) {
            s_poff[e] = acc;
            acc += ((g_counts[e] + 127) >> 7) << 7;
        }
        s_poff[EE] = acc;
        for (int e = 0; e <= EE; e++) g_poff[e] = s_poff[e];
    }
    if (tid < EE) s_cur[tid] = 0;
    __syncthreads();
    if (tid < MTILES) {
        int r = tid << 7;
        int ex = 0;
        for (int e = 0; e < EE; e++)
            if (r >= s_poff[e] && r < s_poff[e + 1]) ex = e;
        g_tile_expert[tid] = ex;
    }
    for (int idx = tid; idx < RROWS; idx += 256) {
        int e = g_tok_e[idx];
        int pos = s_poff[e] + atomicAdd(&s_cur[e], 1);
        g_row_token[pos] = idx >> 1;
        g_tok_pos[idx] = pos;
    }
}

// ---------------------------------------------------------------------------
// Grouped GEMM: R7-proven skeleton, 512 threads / 16 warps (4x4), 32x64 per
// warp. 128x256 tile, BK=32, 2-stage cp.async, in-fragment tf32 cvt.
// WHICH=1: h = relu(gather(z) @ W1[e] + b1) -> g_h
// WHICH=2: y = g_h @ W2[e] + b2             -> g_y
// ---------------------------------------------------------------------------
template <int WHICH>
__global__ __launch_bounds__(NT) void moe_gemm(const float* __restrict__ z,
                                               const float* __restrict__ W_glb,
                                               const float* __restrict__ bias) {
    extern __shared__ __align__(16) float smem[];
    __shared__ int stok[BM];

    const int KDIM = (WHICH == 1) ? DD : HH;
    const int NOUT = (WHICH == 1) ? HH : DD;
    const int NK = KDIM / BK;
    const int bx = blockIdx.x;
    const int n0 = blockIdx.y * BN;
    const int e = g_tile_expert[bx];
    const int row0 = bx * BM;
    const int tid = threadIdx.x, warp = tid >> 5;
    const int wm = warp >> 2, wn = warp & 3;      // 4 x 4 warps, 32 x 64 each

    const float* Wr = W_glb + (size_t)e * KDIM * NOUT;

    if (tid < BM) stok[tid] = (WHICH == 1) ? g_row_token[row0 + tid] : 0;
    __syncthreads();

    const uint32_t sbase = smem_u32(smem);

    // fill: A = 1024 chunks (128 rows x 8), B = 2048 chunks (32 rows x 64)
    auto fill = [&](int kf, int s) {
        uint32_t sa = sbase + s * STG * 4;
        uint32_t sb = sa + ASZ * 4;
        int k0 = kf * BK;
#pragma unroll
        for (int rep = 0; rep < 6; rep++) {
            int i = rep * NT + tid;
            if (i < 1024) {
                int row = i >> 3, q = i & 7;
                uint32_t dst = sa + (row * ASTR + q * 4) * 4;
                if (WHICH == 1) {
                    int tok = stok[row];
                    const float* src = (tok < 0) ? z
                        : z + (size_t)tok * DD + k0 + q * 4;
                    cpa16(dst, src, tok < 0 ? 0u : 16u);
                } else {
                    cpa16(dst, g_h + (size_t)(row0 + row) * HH + k0 + q * 4, 16u);
                }
            } else {
                int j = i - 1024;
                int r = j >> 6, c = j & 63;
                uint32_t dst = sb + (r * BSTR + c * 4) * 4;
                cpa16(dst, Wr + (size_t)(k0 + r) * NOUT + n0 + c * 4, 16u);
            }
        }
    };

    FragC acc[2][4];
#pragma unroll
    for (int i = 0; i < 2; i++)
#pragma unroll
        for (int j = 0; j < 4; j++) wmma::fill_fragment(acc[i][j], 0.0f);

    fill(0, 0);
    CPA_COMMIT();                                 // G0

    for (int kt = 0; kt < NK; kt++) {
        if (kt + 1 < NK) fill(kt + 1, (kt + 1) & 1);
        CPA_COMMIT();                             // G_{kt+1}
        CPA_WAIT1();                              // G0..G_kt complete
        __syncthreads();
        const float* sA = smem + (kt & 1) * STG;
        const float* sB = sA + ASZ;
#pragma unroll
        for (int ks = 0; ks < BK / 8; ks++) {
            FragA a[2]; FragB b[4];
#pragma unroll
            for (int i = 0; i < 2; i++) {
                wmma::load_matrix_sync(a[i], sA + (wm * 32 + i * 16) * ASTR + ks * 8, ASTR);
#pragma unroll
                for (int t = 0; t < a[i].num_elements; t++)
                    a[i].x[t] = wmma::__float_to_tf32(a[i].x[t]);
            }
#pragma unroll
            for (int j = 0; j < 4; j++) {
                wmma::load_matrix_sync(b[j], sB + (ks * 8) * BSTR + wn * 64 + j * 16, BSTR);
#pragma unroll
                for (int t = 0; t < b[j].num_elements; t++)
                    b[j].x[t] = wmma::__float_to_tf32(b[j].x[t]);
            }
#pragma unroll
            for (int i = 0; i < 2; i++)
#pragma unroll
                for (int j = 0; j < 4; j++)
                    wmma::mma_sync(acc[i][j], a[i], b[j], acc[i][j]);
        }
        __syncthreads();
    }

    // ---- epilogue: bias (+relu for GEMM1), direct store, no atomics ----
    CPA_WAIT0();
    __syncthreads();
    for (int i = tid; i < 16 * BN; i += NT) {
        int r = i >> 8, c = i & 255;
        smem[r * BSTR + c] = bias[(size_t)e * NOUT + n0 + c];
    }
    __syncthreads();

    FragC biasf[4];
#pragma unroll
    for (int j = 0; j < 4; j++)
        wmma::load_matrix_sync(biasf[j], smem + wn * 64 + j * 16, BSTR, wmma::mem_row_major);

    float* gdst = (WHICH == 1) ? g_h : g_y;
#pragma unroll
    for (int i = 0; i < 2; i++)
#pragma unroll
        for (int j = 0; j < 4; j++) {
#pragma unroll
            for (int t = 0; t < acc[i][j].num_elements; t++) {
                float v = acc[i][j].x[t] + biasf[j].x[t];
                if (WHICH == 1) v = fmaxf(v, 0.0f);
                acc[i][j].x[t] = v;
            }
            wmma::store_matrix_sync(
                gdst + (size_t)(row0 + wm * 32 + i * 16) * NOUT + n0 + wn * 64 + j * 16,
                acc[i][j], NOUT, wmma::mem_row_major);
        }
}

// out[t] = w0 * y[p0] + w1 * y[p1]
__global__ void combine_kernel(float* __restrict__ out) {
    int idx = blockIdx.x * blockDim.x + threadIdx.x;   // BB*256 float4 units
    int t = idx >> 8, j = idx & 255;
    int p0 = g_tok_pos[2 * t], p1 = g_tok_pos[2 * t + 1];
    float w0 = g_tok_w[2 * t], w1 = g_tok_w[2 * t + 1];
    float4 a = ((const float4*)(g_y + (size_t)p0 * DD))[j];
    float4 b = ((const float4*)(g_y + (size_t)p1 * DD))[j];
    float4 o;
    o.x = w0 * a.x + w1 * b.x;
    o.y = w0 * a.y + w1 * b.y;
    o.z = w0 * a.z + w1 * b.z;
    o.w = w0 * a.w + w1 * b.w;
    ((float4*)out)[idx] = o;
}

// ---------------------------------------------------------------------------
extern "C" void kernel_launch(void* const* d_in, const int* in_sizes, int n_in,
                              void* d_out, int out_size) {
    const float* z  = (const float*)d_in[0];
    const float* Wg = (const float*)d_in[1];
    const float* bg = (const float*)d_in[2];
    const float* W1 = (const float*)d_in[3];
    const float* b1 = (const float*)d_in[4];
    const float* W2 = (const float*)d_in[5];
    const float* b2 = (const float*)d_in[6];
    float* out = (float*)d_out;

    cudaFuncSetAttribute(moe_gemm<1>, cudaFuncAttributeMaxDynamicSharedMemorySize, SMEMSZ);
    cudaFuncSetAttribute(moe_gemm<2>, cudaFuncAttributeMaxDynamicSharedMemorySize, SMEMSZ);

    init_kernel<<<(RPAD + 255) / 256, 256>>>();                        // #0
    gate_kernel<<<BB / 8, 256>>>(z, Wg, bg);                           // #1
    route_kernel<<<1, 256>>>();                                        // #2
    moe_gemm<1><<<dim3(MTILES, HH / BN), NT, SMEMSZ>>>(z, W1, b1);     // #3 <- ncu
    moe_gemm<2><<<dim3(MTILES, DD / BN), NT, SMEMSZ>>>(z, W2, b2);     // #4
    combine_kernel<<<BB, 256>>>(out);                                  // #5
}

// round 13
// speedup vs baseline: 3.2939x; 3.2939x over previous
#include <cuda_runtime.h>
#include <cuda_fp16.h>
#include <cstdint>
#include <mma.h>

using namespace nvcuda;

#define BB 8192
#define DD 1024
#define EE 8
#define HH 4096
#define RROWS (BB * 2)
#define RPAD  17408              // 16384 + 8*128 pad
#define MTILES 136               // RPAD / 128

#define BM 128
#define BN 256
#define BK 32
#define ASTRH 40                         // A stride (halfs): 32 + 8 pad (80 B)
#define BSTRH 264                        // B stride (halfs): 256 + 8 pad (528 B)
#define ABYTESH (BM * ASTRH * 2)         // 10240 B
#define STGBH (ABYTESH + BK * BSTRH * 2) // 27136 B (multiple of 128)
#define SMEMSZ (2 * STGBH)               // 54272 B

// ---------------- device scratch ----------------
__device__ int    g_tok_e[RROWS];
__device__ float  g_tok_w[RROWS];
__device__ int    g_tok_pos[RROWS];
__device__ int    g_counts[EE];
__device__ int    g_poff[EE + 1];
__device__ int    g_row_token[RPAD];
__device__ int    g_tile_expert[MTILES];
__device__ __half g_zh[(size_t)BB * DD];
__device__ __half g_w1h[(size_t)EE * DD * HH];
__device__ __half g_w2h[(size_t)EE * HH * DD];
__device__ float  g_h[(size_t)RPAD * HH];
__device__ __half g_hh[(size_t)RPAD * HH];
__device__ float  g_y[(size_t)RPAD * DD];

typedef wmma::fragment<wmma::matrix_a, 16, 16, 16, __half, wmma::row_major> HFragA;
typedef wmma::fragment<wmma::matrix_b, 16, 16, 16, __half, wmma::row_major> HFragB;
typedef wmma::fragment<wmma::accumulator, 16, 16, 16, float> HFragC;

__device__ __forceinline__ uint32_t smem_u32(const void* p) {
    uint32_t a;
    asm("{ .reg .u64 t; cvta.to.shared.u64 t, %1; cvt.u32.u64 %0, t; }" : "=r"(a) : "l"(p));
    return a;
}
__device__ __forceinline__ void cpa16(uint32_t dst, const void* src, uint32_t sz) {
    asm volatile("cp.async.cg.shared.global [%0], [%1], 16, %2;" :: "r"(dst), "l"(src), "r"(sz));
}
#define CPA_COMMIT() asm volatile("cp.async.commit_group;")
#define CPA_WAIT1()  asm volatile("cp.async.wait_group 1;")
#define CPA_WAIT0()  asm volatile("cp.async.wait_group 0;")

__device__ __forceinline__ void conv4(const float* __restrict__ s, __half* __restrict__ d) {
    float4 v = *(const float4*)s;
    __half2 h0 = __floats2half2_rn(v.x, v.y);
    __half2 h1 = __floats2half2_rn(v.z, v.w);
    uint2 o; o.x = *(uint32_t*)&h0; o.y = *(uint32_t*)&h1;
    *reinterpret_cast<uint2*>(d) = o;
}

// ---------------------------------------------------------------------------
// init: z -> g_zh, W1 -> g_w1h, W2 -> g_w2h (dests via device symbols ONLY),
// reset routing scratch. BB*DD = 8M threads; each converts 1 z + 4 W1 + 4 W2.
__global__ void init_kernel(const float* __restrict__ z,
                            const float* __restrict__ W1,
                            const float* __restrict__ W2) {
    int idx = blockIdx.x * blockDim.x + threadIdx.x;
    g_zh[idx] = __float2half_rn(z[idx]);
    size_t base = (size_t)idx * 4;
    conv4(W1 + base, g_w1h + base);
    conv4(W2 + base, g_w2h + base);
    if (idx < RPAD) g_row_token[idx] = -1;
    if (idx < EE)   g_counts[idx] = 0;
}

// g_h (float) -> g_hh (half); no pointer args at all
__global__ void convH_kernel() {
    size_t i = (size_t)(blockIdx.x * blockDim.x + threadIdx.x) * 8;
    conv4(g_h + i, g_hh + i);
    conv4(g_h + i + 4, g_hh + i + 4);
}

// ---------------------------------------------------------------------------
__global__ __launch_bounds__(256) void gate_kernel(const float* __restrict__ z,
                                                   const float* __restrict__ Wg,
                                                   const float* __restrict__ bg) {
    __shared__ float sWgT[EE * DD];
    int tid = threadIdx.x;
    for (int i = tid; i < DD * EE; i += 256) {
        int d = i >> 3, e = i & 7;
        sWgT[e * DD + d] = Wg[i];
    }
    __syncthreads();
    int warp = tid >> 5, lane = tid & 31;
    int t = blockIdx.x * 8 + warp;
    const float* zrow = z + (size_t)t * DD;
    float acc[EE];
#pragma unroll
    for (int e = 0; e < EE; e++) acc[e] = 0.0f;
    for (int d = lane; d < DD; d += 32) {
        float zv = zrow[d];
#pragma unroll
        for (int e = 0; e < EE; e++) acc[e] += zv * sWgT[e * DD + d];
    }
#pragma unroll
    for (int e = 0; e < EE; e++)
#pragma unroll
        for (int off = 16; off; off >>= 1)
            acc[e] += __shfl_xor_sync(0xffffffffu, acc[e], off);
    if (lane == 0) {
        float l[EE], m = -1e30f;
#pragma unroll
        for (int e = 0; e < EE; e++) { l[e] = acc[e] + bg[e]; m = fmaxf(m, l[e]); }
        float p[EE], Z = 0.0f;
#pragma unroll
        for (int e = 0; e < EE; e++) { p[e] = expf(l[e] - m); Z += p[e]; }
        float b1v = -1.0f, b2v = -1.0f; int i1 = 0, i2 = 0;
#pragma unroll
        for (int e = 0; e < EE; e++) {
            if (p[e] > b1v)      { b2v = b1v; i2 = i1; b1v = p[e]; i1 = e; }
            else if (p[e] > b2v) { b2v = p[e]; i2 = e; }
        }
        float invZ = 1.0f / Z;
        g_tok_e[t * 2 + 0] = i1;  g_tok_w[t * 2 + 0] = b1v * invZ;
        g_tok_e[t * 2 + 1] = i2;  g_tok_w[t * 2 + 1] = b2v * invZ;
        atomicAdd(&g_counts[i1], 1);
        atomicAdd(&g_counts[i2], 1);
    }
}

// fused offsets + tile-expert + scatter (single block)
__global__ void route_kernel() {
    __shared__ int s_poff[EE + 1];
    __shared__ int s_cur[EE];
    int tid = threadIdx.x;
    if (tid == 0) {
        int acc = 0;
        for (int e = 0; e < EE; e++) {
            s_poff[e] = acc;
            acc += ((g_counts[e] + 127) >> 7) << 7;
        }
        s_poff[EE] = acc;
        for (int e = 0; e <= EE; e++) g_poff[e] = s_poff[e];
    }
    if (tid < EE) s_cur[tid] = 0;
    __syncthreads();
    if (tid < MTILES) {
        int r = tid << 7;
        int ex = 0;
        for (int e = 0; e < EE; e++)
            if (r >= s_poff[e] && r < s_poff[e + 1]) ex = e;
        g_tile_expert[tid] = ex;
    }
    for (int idx = tid; idx < RROWS; idx += 256) {
        int e = g_tok_e[idx];
        int pos = s_poff[e] + atomicAdd(&s_cur[e], 1);
        g_row_token[pos] = idx >> 1;
        g_tok_pos[idx] = pos;
    }
}

// ---------------------------------------------------------------------------
// fp16 grouped GEMM, R7-proven 2-stage cp.async skeleton. 128x256 tile, BK=32,
// 8 warps (2x4) of 64x64, m16n16k16 HMMA, fp32 accum. All global tensors
// referenced via device symbols in device code; only bias is a kernel arg.
// WHICH=1: g_h = relu(gather(g_zh) @ g_w1h[e] + b1)   (float out)
// WHICH=2: g_y = g_hh @ g_w2h[e] + b2                 (float out)
// ---------------------------------------------------------------------------
template <int WHICH>
__global__ __launch_bounds__(256) void moe_gemm(const float* __restrict__ bias) {
    extern __shared__ __align__(128) char smemc[];
    __shared__ int stok[BM];

    const int KDIM = (WHICH == 1) ? DD : HH;
    const int NOUT = (WHICH == 1) ? HH : DD;
    const int NK = KDIM / BK;
    const int bx = blockIdx.x;
    const int n0 = blockIdx.y * BN;
    const int e = g_tile_expert[bx];
    const int row0 = bx * BM;
    const int tid = threadIdx.x, warp = tid >> 5;
    const int wm = warp >> 2, wn = warp & 3;

    const __half* Wr = ((WHICH == 1) ? g_w1h : g_w2h) + (size_t)e * KDIM * NOUT;

    if (tid < BM) stok[tid] = (WHICH == 1) ? g_row_token[row0 + tid] : 0;
    __syncthreads();

    const uint32_t sbase = smem_u32(smemc);

    // fill: A = 512 chunks (128 rows x 4), B = 1024 chunks (32 rows x 32)
    auto fill = [&](int kf, int s) {
        uint32_t sa = sbase + s * STGBH;
        uint32_t sb = sa + ABYTESH;
        int k0 = kf * BK;
#pragma unroll
        for (int rep = 0; rep < 6; rep++) {
            int i = rep * 256 + tid;
            if (i < 512) {
                int row = i >> 2, q = i & 3;
                uint32_t dst = sa + row * (ASTRH * 2) + q * 16;
                if (WHICH == 1) {
                    int tok = stok[row];
                    const __half* src = (tok < 0) ? (const __half*)g_zh
                        : g_zh + (size_t)tok * DD + k0 + q * 8;
                    cpa16(dst, src, tok < 0 ? 0u : 16u);
                } else {
                    cpa16(dst, g_hh + (size_t)(row0 + row) * HH + k0 + q * 8, 16u);
                }
            } else {
                int j = i - 512;
                int r = j >> 5, c = j & 31;
                uint32_t dst = sb + r * (BSTRH * 2) + c * 16;
                cpa16(dst, Wr + (size_t)(k0 + r) * NOUT + n0 + c * 8, 16u);
            }
        }
    };

    HFragC acc[4][4];
#pragma unroll
    for (int i = 0; i < 4; i++)
#pragma unroll
        for (int j = 0; j < 4; j++) wmma::fill_fragment(acc[i][j], 0.0f);

    fill(0, 0);
    CPA_COMMIT();                                 // G0

    for (int kt = 0; kt < NK; kt++) {
        if (kt + 1 < NK) fill(kt + 1, (kt + 1) & 1);
        CPA_COMMIT();                             // G_{kt+1}
        CPA_WAIT1();                              // G0..G_kt complete
        __syncthreads();
        const __half* sA = (const __half*)(smemc + (kt & 1) * STGBH);
        const __half* sB = (const __half*)(smemc + (kt & 1) * STGBH + ABYTESH);
#pragma unroll
        for (int ks = 0; ks < BK / 16; ks++) {
            HFragA a[4]; HFragB b[4];
#pragma unroll
            for (int i = 0; i < 4; i++)
                wmma::load_matrix_sync(a[i], sA + (wm * 64 + i * 16) * ASTRH + ks * 16, ASTRH);
#pragma unroll
            for (int j = 0; j < 4; j++)
                wmma::load_matrix_sync(b[j], sB + (ks * 16) * BSTRH + wn * 64 + j * 16, BSTRH);
#pragma unroll
            for (int i = 0; i < 4; i++)
#pragma unroll
                for (int j = 0; j < 4; j++)
                    wmma::mma_sync(acc[i][j], a[i], b[j], acc[i][j]);
        }
        __syncthreads();
    }

    // ---- epilogue: bias (+relu for GEMM1), float store, no atomics ----
    CPA_WAIT0();
    __syncthreads();
    float* sf = (float*)smemc;
    for (int i = tid; i < 16 * BN; i += 256) {
        int r = i >> 8, c = i & 255;
        sf[r * 264 + c] = bias[(size_t)e * NOUT + n0 + c];
    }
    __syncthreads();

    HFragC biasf[4];
#pragma unroll
    for (int j = 0; j < 4; j++)
        wmma::load_matrix_sync(biasf[j], sf + wn * 64 + j * 16, 264, wmma::mem_row_major);

    float* gdst = (WHICH == 1) ? g_h : g_y;
#pragma unroll
    for (int i = 0; i < 4; i++)
#pragma unroll
        for (int j = 0; j < 4; j++) {
#pragma unroll
            for (int t = 0; t < acc[i][j].num_elements; t++) {
                float v = acc[i][j].x[t] + biasf[j].x[t];
                if (WHICH == 1) v = fmaxf(v, 0.0f);
                acc[i][j].x[t] = v;
            }
            wmma::store_matrix_sync(
                gdst + (size_t)(row0 + wm * 64 + i * 16) * NOUT + n0 + wn * 64 + j * 16,
                acc[i][j], NOUT, wmma::mem_row_major);
        }
}

// out[t] = w0 * y[p0] + w1 * y[p1]
__global__ void combine_kernel(float* __restrict__ out) {
    int idx = blockIdx.x * blockDim.x + threadIdx.x;   // BB*256 float4 units
    int t = idx >> 8, j = idx & 255;
    int p0 = g_tok_pos[2 * t], p1 = g_tok_pos[2 * t + 1];
    float w0 = g_tok_w[2 * t], w1 = g_tok_w[2 * t + 1];
    float4 a = ((const float4*)(g_y + (size_t)p0 * DD))[j];
    float4 b = ((const float4*)(g_y + (size_t)p1 * DD))[j];
    float4 o;
    o.x = w0 * a.x + w1 * b.x;
    o.y = w0 * a.y + w1 * b.y;
    o.z = w0 * a.z + w1 * b.z;
    o.w = w0 * a.w + w1 * b.w;
    ((float4*)out)[idx] = o;
}

// ---------------------------------------------------------------------------
extern "C" void kernel_launch(void* const* d_in, const int* in_sizes, int n_in,
                              void* d_out, int out_size) {
    const float* z  = (const float*)d_in[0];
    const float* Wg = (const float*)d_in[1];
    const float* bg = (const float*)d_in[2];
    const float* W1 = (const float*)d_in[3];
    const float* b1 = (const float*)d_in[4];
    const float* W2 = (const float*)d_in[5];
    const float* b2 = (const float*)d_in[6];
    float* out = (float*)d_out;

    cudaFuncSetAttribute(moe_gemm<1>, cudaFuncAttributeMaxDynamicSharedMemorySize, SMEMSZ);
    cudaFuncSetAttribute(moe_gemm<2>, cudaFuncAttributeMaxDynamicSharedMemorySize, SMEMSZ);

    init_kernel<<<BB * DD / 256, 256>>>(z, W1, W2);                   // #0
    gate_kernel<<<BB / 8, 256>>>(z, Wg, bg);                          // #1
    route_kernel<<<1, 256>>>();                                       // #2
    moe_gemm<1><<<dim3(MTILES, HH / BN), 256, SMEMSZ>>>(b1);          // #3 <- ncu
    convH_kernel<<<(int)(((size_t)RPAD * HH / 8) / 256), 256>>>();    // #4
    moe_gemm<2><<<dim3(MTILES, DD / BN), 256, SMEMSZ>>>(b2);          // #5
    combine_kernel<<<BB, 256>>>(out);                                 // #6
}

// round 14
// speedup vs baseline: 3.3458x; 1.0158x over previous
#include <cuda_runtime.h>
#include <cuda_fp16.h>
#include <cstdint>
#include <mma.h>

using namespace nvcuda;

#define BB 8192
#define DD 1024
#define EE 8
#define HH 4096
#define RROWS (BB * 2)
#define RPAD  17408              // 16384 + 8*128 pad
#define MTILES 136               // RPAD / 128

#define BM 128
#define BN 256
#define BK 32
#define NSTG 3
#define ASTRH 40                         // A stride (halfs): 32 + 8 pad (80 B)
#define BSTRH 264                        // B stride (halfs): 256 + 8 pad (528 B)
#define ABYTESH (BM * ASTRH * 2)         // 10240 B
#define STGBH (ABYTESH + BK * BSTRH * 2) // 27136 B (multiple of 128)
#define SMEMSZ (NSTG * STGBH)            // 81408 B

// ---------------- device scratch ----------------
__device__ int    g_tok_e[RROWS];
__device__ float  g_tok_w[RROWS];
__device__ int    g_tok_pos[RROWS];
__device__ int    g_counts[EE];
__device__ int    g_poff[EE + 1];
__device__ int    g_row_token[RPAD];
__device__ int    g_tile_expert[MTILES];
__device__ __half g_zh[(size_t)BB * DD];
__device__ __half g_w1h[(size_t)EE * DD * HH];
__device__ __half g_w2h[(size_t)EE * HH * DD];
__device__ __half g_hh[(size_t)RPAD * HH];
__device__ float  g_y[(size_t)RPAD * DD];

typedef wmma::fragment<wmma::matrix_a, 16, 16, 16, __half, wmma::row_major> HFragA;
typedef wmma::fragment<wmma::matrix_b, 16, 16, 16, __half, wmma::row_major> HFragB;
typedef wmma::fragment<wmma::accumulator, 16, 16, 16, float> HFragC;

__device__ __forceinline__ uint32_t smem_u32(const void* p) {
    uint32_t a;
    asm("{ .reg .u64 t; cvta.to.shared.u64 t, %1; cvt.u32.u64 %0, t; }" : "=r"(a) : "l"(p));
    return a;
}
__device__ __forceinline__ void cpa16(uint32_t dst, const void* src, uint32_t sz) {
    asm volatile("cp.async.cg.shared.global [%0], [%1], 16, %2;" :: "r"(dst), "l"(src), "r"(sz));
}
#define CPA_COMMIT() asm volatile("cp.async.commit_group;")
#define CPA_WAIT2()  asm volatile("cp.async.wait_group 2;")
#define CPA_WAIT0()  asm volatile("cp.async.wait_group 0;")

__device__ __forceinline__ void conv4(const float* __restrict__ s, __half* __restrict__ d) {
    float4 v = *(const float4*)s;
    __half2 h0 = __floats2half2_rn(v.x, v.y);
    __half2 h1 = __floats2half2_rn(v.z, v.w);
    uint2 o; o.x = *(uint32_t*)&h0; o.y = *(uint32_t*)&h1;
    *reinterpret_cast<uint2*>(d) = o;
}

// ---------------------------------------------------------------------------
// init: z -> g_zh, W1 -> g_w1h, W2 -> g_w2h (dests via device symbols ONLY).
__global__ void init_kernel(const float* __restrict__ z,
                            const float* __restrict__ W1,
                            const float* __restrict__ W2) {
    int idx = blockIdx.x * blockDim.x + threadIdx.x;
    g_zh[idx] = __float2half_rn(z[idx]);
    size_t base = (size_t)idx * 4;
    conv4(W1 + base, g_w1h + base);
    conv4(W2 + base, g_w2h + base);
    if (idx < RPAD) g_row_token[idx] = -1;
    if (idx < EE)   g_counts[idx] = 0;
}

// ---------------------------------------------------------------------------
__global__ __launch_bounds__(256) void gate_kernel(const float* __restrict__ z,
                                                   const float* __restrict__ Wg,
                                                   const float* __restrict__ bg) {
    __shared__ float sWgT[EE * DD];
    int tid = threadIdx.x;
    for (int i = tid; i < DD * EE; i += 256) {
        int d = i >> 3, e = i & 7;
        sWgT[e * DD + d] = Wg[i];
    }
    __syncthreads();
    int warp = tid >> 5, lane = tid & 31;
    int t = blockIdx.x * 8 + warp;
    const float* zrow = z + (size_t)t * DD;
    float acc[EE];
#pragma unroll
    for (int e = 0; e < EE; e++) acc[e] = 0.0f;
    for (int d = lane; d < DD; d += 32) {
        float zv = zrow[d];
#pragma unroll
        for (int e = 0; e < EE; e++) acc[e] += zv * sWgT[e * DD + d];
    }
#pragma unroll
    for (int e = 0; e < EE; e++)
#pragma unroll
        for (int off = 16; off; off >>= 1)
            acc[e] += __shfl_xor_sync(0xffffffffu, acc[e], off);
    if (lane == 0) {
        float l[EE], m = -1e30f;
#pragma unroll
        for (int e = 0; e < EE; e++) { l[e] = acc[e] + bg[e]; m = fmaxf(m, l[e]); }
        float p[EE], Z = 0.0f;
#pragma unroll
        for (int e = 0; e < EE; e++) { p[e] = expf(l[e] - m); Z += p[e]; }
        float b1v = -1.0f, b2v = -1.0f; int i1 = 0, i2 = 0;
#pragma unroll
        for (int e = 0; e < EE; e++) {
            if (p[e] > b1v)      { b2v = b1v; i2 = i1; b1v = p[e]; i1 = e; }
            else if (p[e] > b2v) { b2v = p[e]; i2 = e; }
        }
        float invZ = 1.0f / Z;
        g_tok_e[t * 2 + 0] = i1;  g_tok_w[t * 2 + 0] = b1v * invZ;
        g_tok_e[t * 2 + 1] = i2;  g_tok_w[t * 2 + 1] = b2v * invZ;
        atomicAdd(&g_counts[i1], 1);
        atomicAdd(&g_counts[i2], 1);
    }
}

// fused offsets + tile-expert + scatter (single block)
__global__ void route_kernel() {
    __shared__ int s_poff[EE + 1];
    __shared__ int s_cur[EE];
    int tid = threadIdx.x;
    if (tid == 0) {
        int acc = 0;
        for (int e = 0; e < EE; e++) {
            s_poff[e] = acc;
            acc += ((g_counts[e] + 127) >> 7) << 7;
        }
        s_poff[EE] = acc;
        for (int e = 0; e <= EE; e++) g_poff[e] = s_poff[e];
    }
    if (tid < EE) s_cur[tid] = 0;
    __syncthreads();
    if (tid < MTILES) {
        int r = tid << 7;
        int ex = 0;
        for (int e = 0; e < EE; e++)
            if (r >= s_poff[e] && r < s_poff[e + 1]) ex = e;
        g_tile_expert[tid] = ex;
    }
    for (int idx = tid; idx < RROWS; idx += 256) {
        int e = g_tok_e[idx];
        int pos = s_poff[e] + atomicAdd(&s_cur[e], 1);
        g_row_token[pos] = idx >> 1;
        g_tok_pos[idx] = pos;
    }
}

// ---------------------------------------------------------------------------
// fp16 grouped GEMM, 3-stage cp.async. 128x256 tile, BK=32, 8 warps (2x4) of
// 64x64, m16n16k16 HMMA, fp32 accum. Tensors via device symbols only.
// WHICH=1: g_hh = fp16(relu(gather(g_zh) @ g_w1h[e] + b1))  (half out, staged)
// WHICH=2: g_y  = g_hh @ g_w2h[e] + b2                      (float out)
// ---------------------------------------------------------------------------
template <int WHICH>
__global__ __launch_bounds__(256) void moe_gemm(const float* __restrict__ bias) {
    extern __shared__ __align__(128) char smemc[];
    __shared__ int stok[BM];

    const int KDIM = (WHICH == 1) ? DD : HH;
    const int NOUT = (WHICH == 1) ? HH : DD;
    const int NK = KDIM / BK;
    const int bx = blockIdx.x;
    const int n0 = blockIdx.y * BN;
    const int e = g_tile_expert[bx];
    const int row0 = bx * BM;
    const int tid = threadIdx.x, warp = tid >> 5, lane = tid & 31;
    const int wm = warp >> 2, wn = warp & 3;

    const __half* Wr = ((WHICH == 1) ? g_w1h : g_w2h) + (size_t)e * KDIM * NOUT;

    if (tid < BM) stok[tid] = (WHICH == 1) ? g_row_token[row0 + tid] : 0;
    __syncthreads();

    const uint32_t sbase = smem_u32(smemc);

    // fill: A = 512 chunks (128 rows x 4), B = 1024 chunks (32 rows x 32)
    auto fill = [&](int kf, int s) {
        uint32_t sa = sbase + s * STGBH;
        uint32_t sb = sa + ABYTESH;
        int k0 = kf * BK;
#pragma unroll
        for (int rep = 0; rep < 6; rep++) {
            int i = rep * 256 + tid;
            if (i < 512) {
                int row = i >> 2, q = i & 3;
                uint32_t dst = sa + row * (ASTRH * 2) + q * 16;
                if (WHICH == 1) {
                    int tok = stok[row];
                    const __half* src = (tok < 0) ? (const __half*)g_zh
                        : g_zh + (size_t)tok * DD + k0 + q * 8;
                    cpa16(dst, src, tok < 0 ? 0u : 16u);
                } else {
                    cpa16(dst, g_hh + (size_t)(row0 + row) * HH + k0 + q * 8, 16u);
                }
            } else {
                int j = i - 512;
                int r = j >> 5, c = j & 31;
                uint32_t dst = sb + r * (BSTRH * 2) + c * 16;
                cpa16(dst, Wr + (size_t)(k0 + r) * NOUT + n0 + c * 8, 16u);
            }
        }
    };

    HFragC acc[4][4];
#pragma unroll
    for (int i = 0; i < 4; i++)
#pragma unroll
        for (int j = 0; j < 4; j++) wmma::fill_fragment(acc[i][j], 0.0f);

    fill(0, 0);
    CPA_COMMIT();                                 // G0
    fill(1, 1);
    CPA_COMMIT();                                 // G1

    for (int kt = 0; kt < NK; kt++) {
        if (kt + 2 < NK) fill(kt + 2, (kt + 2) % NSTG);
        CPA_COMMIT();                             // G_{kt+2} (empty near end)
        CPA_WAIT2();                              // G0..G_kt complete
        __syncthreads();
        const __half* sA = (const __half*)(smemc + (kt % NSTG) * STGBH);
        const __half* sB = (const __half*)(smemc + (kt % NSTG) * STGBH + ABYTESH);
#pragma unroll
        for (int ks = 0; ks < BK / 16; ks++) {
            HFragA a[4]; HFragB b[4];
#pragma unroll
            for (int i = 0; i < 4; i++)
                wmma::load_matrix_sync(a[i], sA + (wm * 64 + i * 16) * ASTRH + ks * 16, ASTRH);
#pragma unroll
            for (int j = 0; j < 4; j++)
                wmma::load_matrix_sync(b[j], sB + (ks * 16) * BSTRH + wn * 64 + j * 16, BSTRH);
#pragma unroll
            for (int i = 0; i < 4; i++)
#pragma unroll
                for (int j = 0; j < 4; j++)
                    wmma::mma_sync(acc[i][j], a[i], b[j], acc[i][j]);
        }
        __syncthreads();
    }

    // ---- epilogue ----
    CPA_WAIT0();
    __syncthreads();
    float* sf = (float*)smemc;
    for (int i = tid; i < 16 * BN; i += 256) {
        int r = i >> 8, c = i & 255;
        sf[r * 264 + c] = bias[(size_t)e * NOUT + n0 + c];
    }
    __syncthreads();

    HFragC biasf[4];
#pragma unroll
    for (int j = 0; j < 4; j++)
        wmma::load_matrix_sync(biasf[j], sf + wn * 64 + j * 16, 264, wmma::mem_row_major);
    __syncthreads();   // bias in regs; smem reusable for staging

#pragma unroll
    for (int i = 0; i < 4; i++)
#pragma unroll
        for (int j = 0; j < 4; j++)
#pragma unroll
            for (int t = 0; t < acc[i][j].num_elements; t++) {
                float v = acc[i][j].x[t] + biasf[j].x[t];
                if (WHICH == 1) v = fmaxf(v, 0.0f);
                acc[i][j].x[t] = v;
            }

    if (WHICH == 2) {
#pragma unroll
        for (int i = 0; i < 4; i++)
#pragma unroll
            for (int j = 0; j < 4; j++)
                wmma::store_matrix_sync(
                    g_y + (size_t)(row0 + wm * 64 + i * 16) * DD + n0 + wn * 64 + j * 16,
                    acc[i][j], DD, wmma::mem_row_major);
    } else {
        // stage fp32 frag -> convert fp16 -> g_hh  (per-warp smem buffer)
        float* buf = sf + warp * 384;              // 16 rows x 24 floats
        const int r = lane >> 1, c0 = (lane & 1) * 8;
#pragma unroll
        for (int i = 0; i < 4; i++)
#pragma unroll
            for (int j = 0; j < 4; j++) {
                wmma::store_matrix_sync(buf, acc[i][j], 24, wmma::mem_row_major);
                __syncwarp();
                const float* s = buf + r * 24 + c0;
                __half hv[8];
#pragma unroll
                for (int k = 0; k < 8; k++) hv[k] = __float2half_rn(s[k]);
                *(uint4*)(g_hh + (size_t)(row0 + wm * 64 + i * 16 + r) * HH
                          + n0 + wn * 64 + j * 16 + c0) = *(const uint4*)hv;
                __syncwarp();
            }
    }
}

// out[t] = w0 * y[p0] + w1 * y[p1]
__global__ void combine_kernel(float* __restrict__ out) {
    int idx = blockIdx.x * blockDim.x + threadIdx.x;   // BB*256 float4 units
    int t = idx >> 8, j = idx & 255;
    int p0 = g_tok_pos[2 * t], p1 = g_tok_pos[2 * t + 1];
    float w0 = g_tok_w[2 * t], w1 = g_tok_w[2 * t + 1];
    float4 a = ((const float4*)(g_y + (size_t)p0 * DD))[j];
    float4 b = ((const float4*)(g_y + (size_t)p1 * DD))[j];
    float4 o;
    o.x = w0 * a.x + w1 * b.x;
    o.y = w0 * a.y + w1 * b.y;
    o.z = w0 * a.z + w1 * b.z;
    o.w = w0 * a.w + w1 * b.w;
    ((float4*)out)[idx] = o;
}

// ---------------------------------------------------------------------------
extern "C" void kernel_launch(void* const* d_in, const int* in_sizes, int n_in,
                              void* d_out, int out_size) {
    const float* z  = (const float*)d_in[0];
    const float* Wg = (const float*)d_in[1];
    const float* bg = (const float*)d_in[2];
    const float* W1 = (const float*)d_in[3];
    const float* b1 = (const float*)d_in[4];
    const float* W2 = (const float*)d_in[5];
    const float* b2 = (const float*)d_in[6];
    float* out = (float*)d_out;

    cudaFuncSetAttribute(moe_gemm<1>, cudaFuncAttributeMaxDynamicSharedMemorySize, SMEMSZ);
    cudaFuncSetAttribute(moe_gemm<2>, cudaFuncAttributeMaxDynamicSharedMemorySize, SMEMSZ);

    init_kernel<<<BB * DD / 256, 256>>>(z, W1, W2);                   // #0
    gate_kernel<<<BB / 8, 256>>>(z, Wg, bg);                          // #1
    route_kernel<<<1, 256>>>();                                       // #2
    moe_gemm<1><<<dim3(MTILES, HH / BN), 256, SMEMSZ>>>(b1);          // #3 <- ncu
    moe_gemm<2><<<dim3(MTILES, DD / BN), 256, SMEMSZ>>>(b2);          // #4
    combine_kernel<<<BB, 256>>>(out);                                 // #5
}

// round 15
// speedup vs baseline: 3.6070x; 1.0781x over previous
#include <cuda_runtime.h>
#include <cuda_fp16.h>
#include <cstdint>
#include <mma.h>

using namespace nvcuda;

#define BB 8192
#define DD 1024
#define EE 8
#define HH 4096
#define RROWS (BB * 2)
#define RPAD  17408              // 16384 + 8*128 pad
#define MTILES 136               // RPAD / 128

#define BM 128
#define BN 256
#define BK 32
#define NSTG 4
#define ASTRH 40                         // A stride (halfs): 32 + 8 pad (80 B)
#define BSTRH 264                        // B stride (halfs): 256 + 8 pad (528 B)
#define ABYTESH (BM * ASTRH * 2)         // 10240 B
#define STGBH (ABYTESH + BK * BSTRH * 2) // 27136 B (multiple of 128)
#define SMEMSZ (NSTG * STGBH)            // 108544 B

// ---------------- device scratch ----------------
__device__ int    g_tok_e[RROWS];
__device__ float  g_tok_w[RROWS];
__device__ int    g_tok_pos[RROWS];
__device__ int    g_counts[EE];
__device__ int    g_poff[EE + 1];
__device__ int    g_row_token[RPAD];
__device__ int    g_tile_expert[MTILES];
__device__ __half g_zh[(size_t)BB * DD];
__device__ __half g_w1h[(size_t)EE * DD * HH];
__device__ __half g_w2h[(size_t)EE * HH * DD];
__device__ __half g_hh[(size_t)RPAD * HH];
__device__ float  g_y[(size_t)RPAD * DD];

typedef wmma::fragment<wmma::matrix_a, 16, 16, 16, __half, wmma::row_major> HFragA;
typedef wmma::fragment<wmma::matrix_b, 16, 16, 16, __half, wmma::row_major> HFragB;
typedef wmma::fragment<wmma::accumulator, 16, 16, 16, float> HFragC;

__device__ __forceinline__ uint32_t smem_u32(const void* p) {
    uint32_t a;
    asm("{ .reg .u64 t; cvta.to.shared.u64 t, %1; cvt.u32.u64 %0, t; }" : "=r"(a) : "l"(p));
    return a;
}
__device__ __forceinline__ void cpa16(uint32_t dst, const void* src, uint32_t sz) {
    asm volatile("cp.async.cg.shared.global [%0], [%1], 16, %2;" :: "r"(dst), "l"(src), "r"(sz));
}
#define CPA_COMMIT() asm volatile("cp.async.commit_group;")
#define CPA_WAIT2()  asm volatile("cp.async.wait_group 2;")
#define CPA_WAIT0()  asm volatile("cp.async.wait_group 0;")

__device__ __forceinline__ void conv4(const float* __restrict__ s, __half* __restrict__ d) {
    float4 v = *(const float4*)s;
    __half2 h0 = __floats2half2_rn(v.x, v.y);
    __half2 h1 = __floats2half2_rn(v.z, v.w);
    uint2 o; o.x = *(uint32_t*)&h0; o.y = *(uint32_t*)&h1;
    *reinterpret_cast<uint2*>(d) = o;
}

// ---------------------------------------------------------------------------
// init: z -> g_zh, W1 -> g_w1h, W2 -> g_w2h (dests via device symbols ONLY).
__global__ void init_kernel(const float* __restrict__ z,
                            const float* __restrict__ W1,
                            const float* __restrict__ W2) {
    int idx = blockIdx.x * blockDim.x + threadIdx.x;
    g_zh[idx] = __float2half_rn(z[idx]);
    size_t base = (size_t)idx * 4;
    conv4(W1 + base, g_w1h + base);
    conv4(W2 + base, g_w2h + base);
    if (idx < RPAD) g_row_token[idx] = -1;
    if (idx < EE)   g_counts[idx] = 0;
}

// ---------------------------------------------------------------------------
__global__ __launch_bounds__(256) void gate_kernel(const float* __restrict__ z,
                                                   const float* __restrict__ Wg,
                                                   const float* __restrict__ bg) {
    __shared__ float sWgT[EE * DD];
    int tid = threadIdx.x;
    for (int i = tid; i < DD * EE; i += 256) {
        int d = i >> 3, e = i & 7;
        sWgT[e * DD + d] = Wg[i];
    }
    __syncthreads();
    int warp = tid >> 5, lane = tid & 31;
    int t = blockIdx.x * 8 + warp;
    const float* zrow = z + (size_t)t * DD;
    float acc[EE];
#pragma unroll
    for (int e = 0; e < EE; e++) acc[e] = 0.0f;
    for (int d = lane; d < DD; d += 32) {
        float zv = zrow[d];
#pragma unroll
        for (int e = 0; e < EE; e++) acc[e] += zv * sWgT[e * DD + d];
    }
#pragma unroll
    for (int e = 0; e < EE; e++)
#pragma unroll
        for (int off = 16; off; off >>= 1)
            acc[e] += __shfl_xor_sync(0xffffffffu, acc[e], off);
    if (lane == 0) {
        float l[EE], m = -1e30f;
#pragma unroll
        for (int e = 0; e < EE; e++) { l[e] = acc[e] + bg[e]; m = fmaxf(m, l[e]); }
        float p[EE], Z = 0.0f;
#pragma unroll
        for (int e = 0; e < EE; e++) { p[e] = expf(l[e] - m); Z += p[e]; }
        float b1v = -1.0f, b2v = -1.0f; int i1 = 0, i2 = 0;
#pragma unroll
        for (int e = 0; e < EE; e++) {
            if (p[e] > b1v)      { b2v = b1v; i2 = i1; b1v = p[e]; i1 = e; }
            else if (p[e] > b2v) { b2v = p[e]; i2 = e; }
        }
        float invZ = 1.0f / Z;
        g_tok_e[t * 2 + 0] = i1;  g_tok_w[t * 2 + 0] = b1v * invZ;
        g_tok_e[t * 2 + 1] = i2;  g_tok_w[t * 2 + 1] = b2v * invZ;
        atomicAdd(&g_counts[i1], 1);
        atomicAdd(&g_counts[i2], 1);
    }
}

// fused offsets + tile-expert + scatter (single block)
__global__ void route_kernel() {
    __shared__ int s_poff[EE + 1];
    __shared__ int s_cur[EE];
    int tid = threadIdx.x;
    if (tid == 0) {
        int acc = 0;
        for (int e = 0; e < EE; e++) {
            s_poff[e] = acc;
            acc += ((g_counts[e] + 127) >> 7) << 7;
        }
        s_poff[EE] = acc;
        for (int e = 0; e <= EE; e++) g_poff[e] = s_poff[e];
    }
    if (tid < EE) s_cur[tid] = 0;
    __syncthreads();
    if (tid < MTILES) {
        int r = tid << 7;
        int ex = 0;
        for (int e = 0; e < EE; e++)
            if (r >= s_poff[e] && r < s_poff[e + 1]) ex = e;
        g_tile_expert[tid] = ex;
    }
    for (int idx = tid; idx < RROWS; idx += 256) {
        int e = g_tok_e[idx];
        int pos = s_poff[e] + atomicAdd(&s_cur[e], 1);
        g_row_token[pos] = idx >> 1;
        g_tok_pos[idx] = pos;
    }
}

// ---------------------------------------------------------------------------
// fp16 grouped GEMM, 4-stage cp.async, ONE barrier per k-tile.
// Iteration kt: wait(G_kt) -> sync -> fill(kt+3) [stage (kt-1)%4, dead since
// all threads passed compute(kt-1) before this barrier] -> commit -> compute.
// 128x256 tile, BK=32, 8 warps (2x4) of 64x64, m16n16k16 HMMA, fp32 accum.
// WHICH=1: g_hh = fp16(relu(gather(g_zh) @ g_w1h[e] + b1))
// WHICH=2: g_y  = g_hh @ g_w2h[e] + b2
// ---------------------------------------------------------------------------
template <int WHICH>
__global__ __launch_bounds__(256) void moe_gemm(const float* __restrict__ bias) {
    extern __shared__ __align__(128) char smemc[];
    __shared__ int stok[BM];

    const int KDIM = (WHICH == 1) ? DD : HH;
    const int NOUT = (WHICH == 1) ? HH : DD;
    const int NK = KDIM / BK;
    const int bx = blockIdx.x;
    const int n0 = blockIdx.y * BN;
    const int e = g_tile_expert[bx];
    const int row0 = bx * BM;
    const int tid = threadIdx.x, warp = tid >> 5, lane = tid & 31;
    const int wm = warp >> 2, wn = warp & 3;

    const __half* Wr = ((WHICH == 1) ? g_w1h : g_w2h) + (size_t)e * KDIM * NOUT;

    if (tid < BM) stok[tid] = (WHICH == 1) ? g_row_token[row0 + tid] : 0;
    __syncthreads();

    const uint32_t sbase = smem_u32(smemc);

    // fill: A = 512 chunks (128 rows x 4), B = 1024 chunks (32 rows x 32)
    auto fill = [&](int kf, int s) {
        uint32_t sa = sbase + s * STGBH;
        uint32_t sb = sa + ABYTESH;
        int k0 = kf * BK;
#pragma unroll
        for (int rep = 0; rep < 6; rep++) {
            int i = rep * 256 + tid;
            if (i < 512) {
                int row = i >> 2, q = i & 3;
                uint32_t dst = sa + row * (ASTRH * 2) + q * 16;
                if (WHICH == 1) {
                    int tok = stok[row];
                    const __half* src = (tok < 0) ? (const __half*)g_zh
                        : g_zh + (size_t)tok * DD + k0 + q * 8;
                    cpa16(dst, src, tok < 0 ? 0u : 16u);
                } else {
                    cpa16(dst, g_hh + (size_t)(row0 + row) * HH + k0 + q * 8, 16u);
                }
            } else {
                int j = i - 512;
                int r = j >> 5, c = j & 31;
                uint32_t dst = sb + r * (BSTRH * 2) + c * 16;
                cpa16(dst, Wr + (size_t)(k0 + r) * NOUT + n0 + c * 8, 16u);
            }
        }
    };

    HFragC acc[4][4];
#pragma unroll
    for (int i = 0; i < 4; i++)
#pragma unroll
        for (int j = 0; j < 4; j++) wmma::fill_fragment(acc[i][j], 0.0f);

    fill(0, 0); CPA_COMMIT();                    // G0
    fill(1, 1); CPA_COMMIT();                    // G1
    fill(2, 2); CPA_COMMIT();                    // G2

    for (int kt = 0; kt < NK; kt++) {
        CPA_WAIT2();                              // pending {G_{kt+1},G_{kt+2}} -> G_kt done
        __syncthreads();                          // all threads see stage kt; stage kt-1 dead
        if (kt + 3 < NK) fill(kt + 3, (kt + 3) % NSTG);
        CPA_COMMIT();                             // G_{kt+3} (empty near end)
        const __half* sA = (const __half*)(smemc + (kt % NSTG) * STGBH);
        const __half* sB = (const __half*)(smemc + (kt % NSTG) * STGBH + ABYTESH);
#pragma unroll
        for (int ks = 0; ks < BK / 16; ks++) {
            HFragA a[4]; HFragB b[4];
#pragma unroll
            for (int i = 0; i < 4; i++)
                wmma::load_matrix_sync(a[i], sA + (wm * 64 + i * 16) * ASTRH + ks * 16, ASTRH);
#pragma unroll
            for (int j = 0; j < 4; j++)
                wmma::load_matrix_sync(b[j], sB + (ks * 16) * BSTRH + wn * 64 + j * 16, BSTRH);
#pragma unroll
            for (int i = 0; i < 4; i++)
#pragma unroll
                for (int j = 0; j < 4; j++)
                    wmma::mma_sync(acc[i][j], a[i], b[j], acc[i][j]);
        }
    }

    // ---- epilogue ----
    CPA_WAIT0();
    __syncthreads();
    float* sf = (float*)smemc;
    for (int i = tid; i < 16 * BN; i += 256) {
        int r = i >> 8, c = i & 255;
        sf[r * 264 + c] = bias[(size_t)e * NOUT + n0 + c];
    }
    __syncthreads();

    HFragC biasf[4];
#pragma unroll
    for (int j = 0; j < 4; j++)
        wmma::load_matrix_sync(biasf[j], sf + wn * 64 + j * 16, 264, wmma::mem_row_major);
    __syncthreads();   // bias in regs; smem reusable for staging

#pragma unroll
    for (int i = 0; i < 4; i++)
#pragma unroll
        for (int j = 0; j < 4; j++)
#pragma unroll
            for (int t = 0; t < acc[i][j].num_elements; t++) {
                float v = acc[i][j].x[t] + biasf[j].x[t];
                if (WHICH == 1) v = fmaxf(v, 0.0f);
                acc[i][j].x[t] = v;
            }

    if (WHICH == 2) {
#pragma unroll
        for (int i = 0; i < 4; i++)
#pragma unroll
            for (int j = 0; j < 4; j++)
                wmma::store_matrix_sync(
                    g_y + (size_t)(row0 + wm * 64 + i * 16) * DD + n0 + wn * 64 + j * 16,
                    acc[i][j], DD, wmma::mem_row_major);
    } else {
        // stage fp32 frag -> convert fp16 -> g_hh  (per-warp smem buffer)
        float* buf = sf + warp * 384;              // 16 rows x 24 floats
        const int r = lane >> 1, c0 = (lane & 1) * 8;
#pragma unroll
        for (int i = 0; i < 4; i++)
#pragma unroll
            for (int j = 0; j < 4; j++) {
                wmma::store_matrix_sync(buf, acc[i][j], 24, wmma::mem_row_major);
                __syncwarp();
                const float* s = buf + r * 24 + c0;
                __half hv[8];
#pragma unroll
                for (int k = 0; k < 8; k++) hv[k] = __float2half_rn(s[k]);
                *(uint4*)(g_hh + (size_t)(row0 + wm * 64 + i * 16 + r) * HH
                          + n0 + wn * 64 + j * 16 + c0) = *(const uint4*)hv;
                __syncwarp();
            }
    }
}

// out[t] = w0 * y[p0] + w1 * y[p1]
__global__ void combine_kernel(float* __restrict__ out) {
    int idx = blockIdx.x * blockDim.x + threadIdx.x;   // BB*256 float4 units
    int t = idx >> 8, j = idx & 255;
    int p0 = g_tok_pos[2 * t], p1 = g_tok_pos[2 * t + 1];
    float w0 = g_tok_w[2 * t], w1 = g_tok_w[2 * t + 1];
    float4 a = ((const float4*)(g_y + (size_t)p0 * DD))[j];
    float4 b = ((const float4*)(g_y + (size_t)p1 * DD))[j];
    float4 o;
    o.x = w0 * a.x + w1 * b.x;
    o.y = w0 * a.y + w1 * b.y;
    o.z = w0 * a.z + w1 * b.z;
    o.w = w0 * a.w + w1 * b.w;
    ((float4*)out)[idx] = o;
}

// ---------------------------------------------------------------------------
extern "C" void kernel_launch(void* const* d_in, const int* in_sizes, int n_in,
                              void* d_out, int out_size) {
    const float* z  = (const float*)d_in[0];
    const float* Wg = (const float*)d_in[1];
    const float* bg = (const float*)d_in[2];
    const float* W1 = (const float*)d_in[3];
    const float* b1 = (const float*)d_in[4];
    const float* W2 = (const float*)d_in[5];
    const float* b2 = (const float*)d_in[6];
    float* out = (float*)d_out;

    cudaFuncSetAttribute(moe_gemm<1>, cudaFuncAttributeMaxDynamicSharedMemorySize, SMEMSZ);
    cudaFuncSetAttribute(moe_gemm<2>, cudaFuncAttributeMaxDynamicSharedMemorySize, SMEMSZ);

    init_kernel<<<BB * DD / 256, 256>>>(z, W1, W2);                   // #0
    gate_kernel<<<BB / 8, 256>>>(z, Wg, bg);                          // #1
    route_kernel<<<1, 256>>>();                                       // #2
    moe_gemm<1><<<dim3(MTILES, HH / BN), 256, SMEMSZ>>>(b1);          // #3 <- ncu
    moe_gemm<2><<<dim3(MTILES, DD / BN), 256, SMEMSZ>>>(b2);          // #4
    combine_kernel<<<BB, 256>>>(out);                                 // #5
}

// round 16
// speedup vs baseline: 3.6429x; 1.0099x over previous
#include <cuda_runtime.h>
#include <cuda_fp16.h>
#include <cstdint>
#include <mma.h>

using namespace nvcuda;

#define BB 8192
#define DD 1024
#define EE 8
#define HH 4096
#define RROWS (BB * 2)
#define RPAD  17408              // 16384 + 8*128 pad
#define MTILES 136               // RPAD / 128

#define BM 128
#define BN 256
#define BK 32
#define NSTG 4
#define ASTRH 40                         // A stride (halfs): 32 + 8 pad (80 B)
#define BSTRH 264                        // B stride (halfs): 256 + 8 pad (528 B)
#define ABYTESH (BM * ASTRH * 2)         // 10240 B
#define STGBH (ABYTESH + BK * BSTRH * 2) // 27136 B (multiple of 128)
#define SMEMSZ (NSTG * STGBH)            // 108544 B

// ---------------- device scratch ----------------
__device__ int    g_tok_e[RROWS];
__device__ float  g_tok_w[RROWS];
__device__ int    g_tok_pos[RROWS];
__device__ int    g_counts[EE];
__device__ int    g_poff[EE + 1];
__device__ int    g_row_token[RPAD];
__device__ int    g_tile_expert[MTILES];
__device__ __half g_zh[(size_t)BB * DD];
__device__ __half g_w1h[(size_t)EE * DD * HH];
__device__ __half g_w2h[(size_t)EE * HH * DD];
__device__ __half g_hh[(size_t)RPAD * HH];
__device__ float  g_y[(size_t)RPAD * DD];

typedef wmma::fragment<wmma::matrix_a, 16, 16, 16, __half, wmma::row_major> HFragA;
typedef wmma::fragment<wmma::matrix_b, 16, 16, 16, __half, wmma::row_major> HFragB;
typedef wmma::fragment<wmma::accumulator, 16, 16, 16, float> HFragC;

__device__ __forceinline__ uint32_t smem_u32(const void* p) {
    uint32_t a;
    asm("{ .reg .u64 t; cvta.to.shared.u64 t, %1; cvt.u32.u64 %0, t; }" : "=r"(a) : "l"(p));
    return a;
}
__device__ __forceinline__ void cpa16(uint32_t dst, const void* src, uint32_t sz) {
    asm volatile("cp.async.cg.shared.global [%0], [%1], 16, %2;" :: "r"(dst), "l"(src), "r"(sz));
}
#define CPA_COMMIT() asm volatile("cp.async.commit_group;")
#define CPA_WAIT2()  asm volatile("cp.async.wait_group 2;")
#define CPA_WAIT0()  asm volatile("cp.async.wait_group 0;")

__device__ __forceinline__ void conv4(const float* __restrict__ s, __half* __restrict__ d) {
    float4 v = *(const float4*)s;
    __half2 h0 = __floats2half2_rn(v.x, v.y);
    __half2 h1 = __floats2half2_rn(v.z, v.w);
    uint2 o; o.x = *(uint32_t*)&h0; o.y = *(uint32_t*)&h1;
    *reinterpret_cast<uint2*>(d) = o;
}

// ---------------------------------------------------------------------------
// init: z -> g_zh, W1 -> g_w1h, W2 -> g_w2h (dests via device symbols ONLY).
__global__ void init_kernel(const float* __restrict__ z,
                            const float* __restrict__ W1,
                            const float* __restrict__ W2) {
    int idx = blockIdx.x * blockDim.x + threadIdx.x;
    g_zh[idx] = __float2half_rn(z[idx]);
    size_t base = (size_t)idx * 4;
    conv4(W1 + base, g_w1h + base);
    conv4(W2 + base, g_w2h + base);
    if (idx < RPAD) g_row_token[idx] = -1;
    if (idx < EE)   g_counts[idx] = 0;
}

// ---------------------------------------------------------------------------
__global__ __launch_bounds__(256) void gate_kernel(const float* __restrict__ z,
                                                   const float* __restrict__ Wg,
                                                   const float* __restrict__ bg) {
    __shared__ float sWgT[EE * DD];
    int tid = threadIdx.x;
    for (int i = tid; i < DD * EE; i += 256) {
        int d = i >> 3, e = i & 7;
        sWgT[e * DD + d] = Wg[i];
    }
    __syncthreads();
    int warp = tid >> 5, lane = tid & 31;
    int t = blockIdx.x * 8 + warp;
    const float* zrow = z + (size_t)t * DD;
    float acc[EE];
#pragma unroll
    for (int e = 0; e < EE; e++) acc[e] = 0.0f;
    for (int d = lane; d < DD; d += 32) {
        float zv = zrow[d];
#pragma unroll
        for (int e = 0; e < EE; e++) acc[e] += zv * sWgT[e * DD + d];
    }
#pragma unroll
    for (int e = 0; e < EE; e++)
#pragma unroll
        for (int off = 16; off; off >>= 1)
            acc[e] += __shfl_xor_sync(0xffffffffu, acc[e], off);
    if (lane == 0) {
        float l[EE], m = -1e30f;
#pragma unroll
        for (int e = 0; e < EE; e++) { l[e] = acc[e] + bg[e]; m = fmaxf(m, l[e]); }
        float p[EE], Z = 0.0f;
#pragma unroll
        for (int e = 0; e < EE; e++) { p[e] = expf(l[e] - m); Z += p[e]; }
        float b1v = -1.0f, b2v = -1.0f; int i1 = 0, i2 = 0;
#pragma unroll
        for (int e = 0; e < EE; e++) {
            if (p[e] > b1v)      { b2v = b1v; i2 = i1; b1v = p[e]; i1 = e; }
            else if (p[e] > b2v) { b2v = p[e]; i2 = e; }
        }
        float invZ = 1.0f / Z;
        g_tok_e[t * 2 + 0] = i1;  g_tok_w[t * 2 + 0] = b1v * invZ;
        g_tok_e[t * 2 + 1] = i2;  g_tok_w[t * 2 + 1] = b2v * invZ;
        atomicAdd(&g_counts[i1], 1);
        atomicAdd(&g_counts[i2], 1);
    }
}

// fused offsets + tile-expert + scatter (single block)
__global__ void route_kernel() {
    __shared__ int s_poff[EE + 1];
    __shared__ int s_cur[EE];
    int tid = threadIdx.x;
    if (tid == 0) {
        int acc = 0;
        for (int e = 0; e < EE; e++) {
            s_poff[e] = acc;
            acc += ((g_counts[e] + 127) >> 7) << 7;
        }
        s_poff[EE] = acc;
        for (int e = 0; e <= EE; e++) g_poff[e] = s_poff[e];
    }
    if (tid < EE) s_cur[tid] = 0;
    __syncthreads();
    if (tid < MTILES) {
        int r = tid << 7;
        int ex = 0;
        for (int e = 0; e < EE; e++)
            if (r >= s_poff[e] && r < s_poff[e + 1]) ex = e;
        g_tile_expert[tid] = ex;
    }
    for (int idx = tid; idx < RROWS; idx += 256) {
        int e = g_tok_e[idx];
        int pos = s_poff[e] + atomicAdd(&s_cur[e], 1);
        g_row_token[pos] = idx >> 1;
        g_tok_pos[idx] = pos;
    }
}

// ---------------------------------------------------------------------------
// fp16 grouped GEMM, 4-stage cp.async, ONE barrier per k-tile, and
// software-pipelined fragment loads: ks=0 frags -> fill(kt+3) -> ks=1 frags
// -> compute ks=0 -> compute ks=1 (ks1 LDSM latency hidden under ks0 HMMA).
// 128x256 tile, BK=32, 8 warps (2x4) of 64x64, m16n16k16 HMMA, fp32 accum.
// WHICH=1: g_hh = fp16(relu(gather(g_zh) @ g_w1h[e] + b1))
// WHICH=2: g_y  = g_hh @ g_w2h[e] + b2
// ---------------------------------------------------------------------------
template <int WHICH>
__global__ __launch_bounds__(256) void moe_gemm(const float* __restrict__ bias) {
    extern __shared__ __align__(128) char smemc[];
    __shared__ int stok[BM];

    const int KDIM = (WHICH == 1) ? DD : HH;
    const int NOUT = (WHICH == 1) ? HH : DD;
    const int NK = KDIM / BK;
    const int bx = blockIdx.x;
    const int n0 = blockIdx.y * BN;
    const int e = g_tile_expert[bx];
    const int row0 = bx * BM;
    const int tid = threadIdx.x, warp = tid >> 5, lane = tid & 31;
    const int wm = warp >> 2, wn = warp & 3;

    const __half* Wr = ((WHICH == 1) ? g_w1h : g_w2h) + (size_t)e * KDIM * NOUT;

    if (tid < BM) stok[tid] = (WHICH == 1) ? g_row_token[row0 + tid] : 0;
    __syncthreads();

    const uint32_t sbase = smem_u32(smemc);

    // fill: A = 512 chunks (128 rows x 4), B = 1024 chunks (32 rows x 32)
    auto fill = [&](int kf, int s) {
        uint32_t sa = sbase + s * STGBH;
        uint32_t sb = sa + ABYTESH;
        int k0 = kf * BK;
#pragma unroll
        for (int rep = 0; rep < 6; rep++) {
            int i = rep * 256 + tid;
            if (i < 512) {
                int row = i >> 2, q = i & 3;
                uint32_t dst = sa + row * (ASTRH * 2) + q * 16;
                if (WHICH == 1) {
                    int tok = stok[row];
                    const __half* src = (tok < 0) ? (const __half*)g_zh
                        : g_zh + (size_t)tok * DD + k0 + q * 8;
                    cpa16(dst, src, tok < 0 ? 0u : 16u);
                } else {
                    cpa16(dst, g_hh + (size_t)(row0 + row) * HH + k0 + q * 8, 16u);
                }
            } else {
                int j = i - 512;
                int r = j >> 5, c = j & 31;
                uint32_t dst = sb + r * (BSTRH * 2) + c * 16;
                cpa16(dst, Wr + (size_t)(k0 + r) * NOUT + n0 + c * 8, 16u);
            }
        }
    };

    HFragC acc[4][4];
#pragma unroll
    for (int i = 0; i < 4; i++)
#pragma unroll
        for (int j = 0; j < 4; j++) wmma::fill_fragment(acc[i][j], 0.0f);

    fill(0, 0); CPA_COMMIT();                    // G0
    fill(1, 1); CPA_COMMIT();                    // G1
    fill(2, 2); CPA_COMMIT();                    // G2

    for (int kt = 0; kt < NK; kt++) {
        CPA_WAIT2();                              // pending {G_{kt+1},G_{kt+2}} -> G_kt done
        __syncthreads();                          // stage kt visible; stage kt-1 dead
        const __half* sA = (const __half*)(smemc + (kt % NSTG) * STGBH);
        const __half* sB = (const __half*)(smemc + (kt % NSTG) * STGBH + ABYTESH);

        // ks = 0 fragment loads
        HFragA a0[4]; HFragB b0[4];
#pragma unroll
        for (int i = 0; i < 4; i++)
            wmma::load_matrix_sync(a0[i], sA + (wm * 64 + i * 16) * ASTRH, ASTRH);
#pragma unroll
        for (int j = 0; j < 4; j++)
            wmma::load_matrix_sync(b0[j], sB + wn * 64 + j * 16, BSTRH);

        // prefetch next stage (cp.async issue tucked between LDSM batches)
        if (kt + 3 < NK) fill(kt + 3, (kt + 3) % NSTG);
        CPA_COMMIT();                             // G_{kt+3} (empty near end)

        // ks = 1 fragment loads (latency hidden under ks0 HMMAs below)
        HFragA a1[4]; HFragB b1[4];
#pragma unroll
        for (int i = 0; i < 4; i++)
            wmma::load_matrix_sync(a1[i], sA + (wm * 64 + i * 16) * ASTRH + 16, ASTRH);
#pragma unroll
        for (int j = 0; j < 4; j++)
            wmma::load_matrix_sync(b1[j], sB + 16 * BSTRH + wn * 64 + j * 16, BSTRH);

#pragma unroll
        for (int i = 0; i < 4; i++)
#pragma unroll
            for (int j = 0; j < 4; j++)
                wmma::mma_sync(acc[i][j], a0[i], b0[j], acc[i][j]);
#pragma unroll
        for (int i = 0; i < 4; i++)
#pragma unroll
            for (int j = 0; j < 4; j++)
                wmma::mma_sync(acc[i][j], a1[i], b1[j], acc[i][j]);
    }

    // ---- epilogue ----
    CPA_WAIT0();
    __syncthreads();
    float* sf = (float*)smemc;
    for (int i = tid; i < 16 * BN; i += 256) {
        int r = i >> 8, c = i & 255;
        sf[r * 264 + c] = bias[(size_t)e * NOUT + n0 + c];
    }
    __syncthreads();

    HFragC biasf[4];
#pragma unroll
    for (int j = 0; j < 4; j++)
        wmma::load_matrix_sync(biasf[j], sf + wn * 64 + j * 16, 264, wmma::mem_row_major);
    __syncthreads();   // bias in regs; smem reusable for staging

#pragma unroll
    for (int i = 0; i < 4; i++)
#pragma unroll
        for (int j = 0; j < 4; j++)
#pragma unroll
            for (int t = 0; t < acc[i][j].num_elements; t++) {
                float v = acc[i][j].x[t] + biasf[j].x[t];
                if (WHICH == 1) v = fmaxf(v, 0.0f);
                acc[i][j].x[t] = v;
            }

    if (WHICH == 2) {
#pragma unroll
        for (int i = 0; i < 4; i++)
#pragma unroll
            for (int j = 0; j < 4; j++)
                wmma::store_matrix_sync(
                    g_y + (size_t)(row0 + wm * 64 + i * 16) * DD + n0 + wn * 64 + j * 16,
                    acc[i][j], DD, wmma::mem_row_major);
    } else {
        // stage fp32 frag -> convert fp16 -> g_hh  (per-warp smem buffer)
        float* buf = sf + warp * 384;              // 16 rows x 24 floats
        const int r = lane >> 1, c0 = (lane & 1) * 8;
#pragma unroll
        for (int i = 0; i < 4; i++)
#pragma unroll
            for (int j = 0; j < 4; j++) {
                wmma::store_matrix_sync(buf, acc[i][j], 24, wmma::mem_row_major);
                __syncwarp();
                const float* s = buf + r * 24 + c0;
                __half hv[8];
#pragma unroll
                for (int k = 0; k < 8; k++) hv[k] = __float2half_rn(s[k]);
                *(uint4*)(g_hh + (size_t)(row0 + wm * 64 + i * 16 + r) * HH
                          + n0 + wn * 64 + j * 16 + c0) = *(const uint4*)hv;
                __syncwarp();
            }
    }
}

// out[t] = w0 * y[p0] + w1 * y[p1]
__global__ void combine_kernel(float* __restrict__ out) {
    int idx = blockIdx.x * blockDim.x + threadIdx.x;   // BB*256 float4 units
    int t = idx >> 8, j = idx & 255;
    int p0 = g_tok_pos[2 * t], p1 = g_tok_pos[2 * t + 1];
    float w0 = g_tok_w[2 * t], w1 = g_tok_w[2 * t + 1];
    float4 a = ((const float4*)(g_y + (size_t)p0 * DD))[j];
    float4 b = ((const float4*)(g_y + (size_t)p1 * DD))[j];
    float4 o;
    o.x = w0 * a.x + w1 * b.x;
    o.y = w0 * a.y + w1 * b.y;
    o.z = w0 * a.z + w1 * b.z;
    o.w = w0 * a.w + w1 * b.w;
    ((float4*)out)[idx] = o;
}

// ---------------------------------------------------------------------------
extern "C" void kernel_launch(void* const* d_in, const int* in_sizes, int n_in,
                              void* d_out, int out_size) {
    const float* z  = (const float*)d_in[0];
    const float* Wg = (const float*)d_in[1];
    const float* bg = (const float*)d_in[2];
    const float* W1 = (const float*)d_in[3];
    const float* b1 = (const float*)d_in[4];
    const float* W2 = (const float*)d_in[5];
    const float* b2 = (const float*)d_in[6];
    float* out = (float*)d_out;

    cudaFuncSetAttribute(moe_gemm<1>, cudaFuncAttributeMaxDynamicSharedMemorySize, SMEMSZ);
    cudaFuncSetAttribute(moe_gemm<2>, cudaFuncAttributeMaxDynamicSharedMemorySize, SMEMSZ);

    init_kernel<<<BB * DD / 256, 256>>>(z, W1, W2);                   // #0
    gate_kernel<<<BB / 8, 256>>>(z, Wg, bg);                          // #1
    route_kernel<<<1, 256>>>();                                       // #2
    moe_gemm<1><<<dim3(MTILES, HH / BN), 256, SMEMSZ>>>(b1);          // #3 <- ncu
    moe_gemm<2><<<dim3(MTILES, DD / BN), 256, SMEMSZ>>>(b2);          // #4
    combine_kernel<<<BB, 256>>>(out);                                 // #5
}

// round 17
// speedup vs baseline: 3.7685x; 1.0345x over previous
#include <cuda_runtime.h>
#include <cuda_fp16.h>
#include <cstdint>
#include <mma.h>

using namespace nvcuda;

#define BB 8192
#define DD 1024
#define EE 8
#define HH 4096
#define RROWS (BB * 2)
#define RPAD  17408              // 16384 + 8*128 pad
#define MTILES 136               // RPAD / 128

#define BM 128
#define BN 256
#define BK 64
#define NSTG 4
#define ASTRH 72                         // A stride (halfs): 64 + 8 pad (144 B)
#define BSTRH 264                        // B stride (halfs): 256 + 8 pad (528 B)
#define ABYTESH (BM * ASTRH * 2)         // 18432 B
#define STGBH (ABYTESH + BK * BSTRH * 2) // 52224 B (multiple of 128)
#define SMEMSZ (NSTG * STGBH)            // 208896 B

// ---------------- device scratch ----------------
__device__ int    g_tok_e[RROWS];
__device__ float  g_tok_w[RROWS];
__device__ int    g_tok_pos[RROWS];
__device__ int    g_counts[EE];
__device__ int    g_poff[EE + 1];
__device__ int    g_row_token[RPAD];
__device__ int    g_tile_expert[MTILES];
__device__ __half g_zh[(size_t)BB * DD];
__device__ __half g_w1h[(size_t)EE * DD * HH];
__device__ __half g_w2h[(size_t)EE * HH * DD];
__device__ __half g_hh[(size_t)RPAD * HH];
__device__ float  g_y[(size_t)RPAD * DD];

typedef wmma::fragment<wmma::matrix_a, 16, 16, 16, __half, wmma::row_major> HFragA;
typedef wmma::fragment<wmma::matrix_b, 16, 16, 16, __half, wmma::row_major> HFragB;
typedef wmma::fragment<wmma::accumulator, 16, 16, 16, float> HFragC;

__device__ __forceinline__ uint32_t smem_u32(const void* p) {
    uint32_t a;
    asm("{ .reg .u64 t; cvta.to.shared.u64 t, %1; cvt.u32.u64 %0, t; }" : "=r"(a) : "l"(p));
    return a;
}
__device__ __forceinline__ void cpa16(uint32_t dst, const void* src, uint32_t sz) {
    asm volatile("cp.async.cg.shared.global [%0], [%1], 16, %2;" :: "r"(dst), "l"(src), "r"(sz));
}
#define CPA_COMMIT() asm volatile("cp.async.commit_group;")
#define CPA_WAIT2()  asm volatile("cp.async.wait_group 2;")
#define CPA_WAIT0()  asm volatile("cp.async.wait_group 0;")

__device__ __forceinline__ void conv4(const float* __restrict__ s, __half* __restrict__ d) {
    float4 v = *(const float4*)s;
    __half2 h0 = __floats2half2_rn(v.x, v.y);
    __half2 h1 = __floats2half2_rn(v.z, v.w);
    uint2 o; o.x = *(uint32_t*)&h0; o.y = *(uint32_t*)&h1;
    *reinterpret_cast<uint2*>(d) = o;
}

// ---------------------------------------------------------------------------
// init: W1 -> g_w1h, W2 -> g_w2h (dests via device symbols ONLY) + routing.
__global__ void init_kernel(const float* __restrict__ W1,
                            const float* __restrict__ W2) {
    int idx = blockIdx.x * blockDim.x + threadIdx.x;   // EE*DD*HH/4 threads
    size_t base = (size_t)idx * 4;
    conv4(W1 + base, g_w1h + base);
    conv4(W2 + base, g_w2h + base);
    if (idx < RPAD) g_row_token[idx] = -1;
    if (idx < EE)   g_counts[idx] = 0;
}

// ---------------------------------------------------------------------------
// gate: logits/softmax/top-2 AND coalesced z -> g_zh conversion.
__global__ __launch_bounds__(256) void gate_kernel(const float* __restrict__ z,
                                                   const float* __restrict__ Wg,
                                                   const float* __restrict__ bg) {
    __shared__ float sWgT[EE * DD];
    int tid = threadIdx.x;
    for (int i = tid; i < DD * EE; i += 256) {
        int d = i >> 3, e = i & 7;
        sWgT[e * DD + d] = Wg[i];
    }
    __syncthreads();
    int warp = tid >> 5, lane = tid & 31;
    int t = blockIdx.x * 8 + warp;
    const float* zrow = z + (size_t)t * DD;
    float acc[EE];
#pragma unroll
    for (int e = 0; e < EE; e++) acc[e] = 0.0f;
    for (int d = lane; d < DD; d += 32) {
        float zv = zrow[d];
#pragma unroll
        for (int e = 0; e < EE; e++) acc[e] += zv * sWgT[e * DD + d];
    }
    // coalesced fp16 conversion of this token's row (half2 per lane)
    for (int d = lane * 2; d < DD; d += 64) {
        float2 v = *(const float2*)(zrow + d);
        __half2 hv = __floats2half2_rn(v.x, v.y);
        *(__half2*)(g_zh + (size_t)t * DD + d) = hv;
    }
#pragma unroll
    for (int e = 0; e < EE; e++)
#pragma unroll
        for (int off = 16; off; off >>= 1)
            acc[e] += __shfl_xor_sync(0xffffffffu, acc[e], off);
    if (lane == 0) {
        float l[EE], m = -1e30f;
#pragma unroll
        for (int e = 0; e < EE; e++) { l[e] = acc[e] + bg[e]; m = fmaxf(m, l[e]); }
        float p[EE], Z = 0.0f;
#pragma unroll
        for (int e = 0; e < EE; e++) { p[e] = expf(l[e] - m); Z += p[e]; }
        float b1v = -1.0f, b2v = -1.0f; int i1 = 0, i2 = 0;
#pragma unroll
        for (int e = 0; e < EE; e++) {
            if (p[e] > b1v)      { b2v = b1v; i2 = i1; b1v = p[e]; i1 = e; }
            else if (p[e] > b2v) { b2v = p[e]; i2 = e; }
        }
        float invZ = 1.0f / Z;
        g_tok_e[t * 2 + 0] = i1;  g_tok_w[t * 2 + 0] = b1v * invZ;
        g_tok_e[t * 2 + 1] = i2;  g_tok_w[t * 2 + 1] = b2v * invZ;
        atomicAdd(&g_counts[i1], 1);
        atomicAdd(&g_counts[i2], 1);
    }
}

// fused offsets + tile-expert + scatter (single block)
__global__ void route_kernel() {
    __shared__ int s_poff[EE + 1];
    __shared__ int s_cur[EE];
    int tid = threadIdx.x;
    if (tid == 0) {
        int acc = 0;
        for (int e = 0; e < EE; e++) {
            s_poff[e] = acc;
            acc += ((g_counts[e] + 127) >> 7) << 7;
        }
        s_poff[EE] = acc;
        for (int e = 0; e <= EE; e++) g_poff[e] = s_poff[e];
    }
    if (tid < EE) s_cur[tid] = 0;
    __syncthreads();
    if (tid < MTILES) {
        int r = tid << 7;
        int ex = 0;
        for (int e = 0; e < EE; e++)
            if (r >= s_poff[e] && r < s_poff[e + 1]) ex = e;
        g_tile_expert[tid] = ex;
    }
    for (int idx = tid; idx < RROWS; idx += 256) {
        int e = g_tok_e[idx];
        int pos = s_poff[e] + atomicAdd(&s_cur[e], 1);
        g_row_token[pos] = idx >> 1;
        g_tok_pos[idx] = pos;
    }
}

// ---------------------------------------------------------------------------
// fp16 grouped GEMM, 4-stage cp.async, BK=64, ONE barrier per k-tile,
// R15-style mainloop (loads+mma per ks, no frag double-buffer).
// 128x256 tile, 8 warps (2x4) of 64x64, m16n16k16 HMMA, fp32 accum.
// WHICH=1: g_hh = fp16(relu(gather(g_zh) @ g_w1h[e] + b1))
// WHICH=2: g_y  = g_hh @ g_w2h[e] + b2
// ---------------------------------------------------------------------------
template <int WHICH>
__global__ __launch_bounds__(256) void moe_gemm(const float* __restrict__ bias) {
    extern __shared__ __align__(128) char smemc[];
    __shared__ int stok[BM];

    const int KDIM = (WHICH == 1) ? DD : HH;
    const int NOUT = (WHICH == 1) ? HH : DD;
    const int NK = KDIM / BK;                 // 16 / 64
    const int bx = blockIdx.x;
    const int n0 = blockIdx.y * BN;
    const int e = g_tile_expert[bx];
    const int row0 = bx * BM;
    const int tid = threadIdx.x, warp = tid >> 5, lane = tid & 31;
    const int wm = warp >> 2, wn = warp & 3;

    const __half* Wr = ((WHICH == 1) ? g_w1h : g_w2h) + (size_t)e * KDIM * NOUT;

    if (tid < BM) stok[tid] = (WHICH == 1) ? g_row_token[row0 + tid] : 0;
    __syncthreads();

    const uint32_t sbase = smem_u32(smemc);

    // fill: A = 1024 chunks (128 rows x 8), B = 2048 chunks (64 rows x 32)
    auto fill = [&](int kf, int s) {
        uint32_t sa = sbase + s * STGBH;
        uint32_t sb = sa + ABYTESH;
        int k0 = kf * BK;
#pragma unroll
        for (int rep = 0; rep < 12; rep++) {
            int i = rep * 256 + tid;
            if (i < 1024) {
                int row = i >> 3, q = i & 7;
                uint32_t dst = sa + row * (ASTRH * 2) + q * 16;
                if (WHICH == 1) {
                    int tok = stok[row];
                    const __half* src = (tok < 0) ? (const __half*)g_zh
                        : g_zh + (size_t)tok * DD + k0 + q * 8;
                    cpa16(dst, src, tok < 0 ? 0u : 16u);
                } else {
                    cpa16(dst, g_hh + (size_t)(row0 + row) * HH + k0 + q * 8, 16u);
                }
            } else {
                int j = i - 1024;
                int r = j >> 5, c = j & 31;
                uint32_t dst = sb + r * (BSTRH * 2) + c * 16;
                cpa16(dst, Wr + (size_t)(k0 + r) * NOUT + n0 + c * 8, 16u);
            }
        }
    };

    HFragC acc[4][4];
#pragma unroll
    for (int i = 0; i < 4; i++)
#pragma unroll
        for (int j = 0; j < 4; j++) wmma::fill_fragment(acc[i][j], 0.0f);

    fill(0, 0); CPA_COMMIT();                    // G0
    fill(1, 1); CPA_COMMIT();                    // G1
    fill(2, 2); CPA_COMMIT();                    // G2

    for (int kt = 0; kt < NK; kt++) {
        CPA_WAIT2();                              // pending {G_{kt+1},G_{kt+2}} -> G_kt done
        __syncthreads();                          // stage kt visible; stage kt-1 dead
        if (kt + 3 < NK) fill(kt + 3, (kt + 3) % NSTG);
        CPA_COMMIT();                             // G_{kt+3} (empty near end)
        const __half* sA = (const __half*)(smemc + (kt % NSTG) * STGBH);
        const __half* sB = (const __half*)(smemc + (kt % NSTG) * STGBH + ABYTESH);
#pragma unroll
        for (int ks = 0; ks < BK / 16; ks++) {
            HFragA a[4]; HFragB b[4];
#pragma unroll
            for (int i = 0; i < 4; i++)
                wmma::load_matrix_sync(a[i], sA + (wm * 64 + i * 16) * ASTRH + ks * 16, ASTRH);
#pragma unroll
            for (int j = 0; j < 4; j++)
                wmma::load_matrix_sync(b[j], sB + (ks * 16) * BSTRH + wn * 64 + j * 16, BSTRH);
#pragma unroll
            for (int i = 0; i < 4; i++)
#pragma unroll
                for (int j = 0; j < 4; j++)
                    wmma::mma_sync(acc[i][j], a[i], b[j], acc[i][j]);
        }
    }

    // ---- epilogue ----
    CPA_WAIT0();
    __syncthreads();
    float* sf = (float*)smemc;
    for (int i = tid; i < 16 * BN; i += 256) {
        int r = i >> 8, c = i & 255;
        sf[r * 264 + c] = bias[(size_t)e * NOUT + n0 + c];
    }
    __syncthreads();

    HFragC biasf[4];
#pragma unroll
    for (int j = 0; j < 4; j++)
        wmma::load_matrix_sync(biasf[j], sf + wn * 64 + j * 16, 264, wmma::mem_row_major);
    __syncthreads();   // bias in regs; smem reusable for staging

#pragma unroll
    for (int i = 0; i < 4; i++)
#pragma unroll
        for (int j = 0; j < 4; j++)
#pragma unroll
            for (int t = 0; t < acc[i][j].num_elements; t++) {
                float v = acc[i][j].x[t] + biasf[j].x[t];
                if (WHICH == 1) v = fmaxf(v, 0.0f);
                acc[i][j].x[t] = v;
            }

    if (WHICH == 2) {
#pragma unroll
        for (int i = 0; i < 4; i++)
#pragma unroll
            for (int j = 0; j < 4; j++)
                wmma::store_matrix_sync(
                    g_y + (size_t)(row0 + wm * 64 + i * 16) * DD + n0 + wn * 64 + j * 16,
                    acc[i][j], DD, wmma::mem_row_major);
    } else {
        // stage fp32 frag -> convert fp16 -> g_hh  (per-warp smem buffer)
        float* buf = sf + warp * 384;              // 16 rows x 24 floats
        const int r = lane >> 1, c0 = (lane & 1) * 8;
#pragma unroll
        for (int i = 0; i < 4; i++)
#pragma unroll
            for (int j = 0; j < 4; j++) {
                wmma::store_matrix_sync(buf, acc[i][j], 24, wmma::mem_row_major);
                __syncwarp();
                const float* s = buf + r * 24 + c0;
                __half hv[8];
#pragma unroll
                for (int k = 0; k < 8; k++) hv[k] = __float2half_rn(s[k]);
                *(uint4*)(g_hh + (size_t)(row0 + wm * 64 + i * 16 + r) * HH
                          + n0 + wn * 64 + j * 16 + c0) = *(const uint4*)hv;
                __syncwarp();
            }
    }
}

// out[t] = w0 * y[p0] + w1 * y[p1]
__global__ void combine_kernel(float* __restrict__ out) {
    int idx = blockIdx.x * blockDim.x + threadIdx.x;   // BB*256 float4 units
    int t = idx >> 8, j = idx & 255;
    int p0 = g_tok_pos[2 * t], p1 = g_tok_pos[2 * t + 1];
    float w0 = g_tok_w[2 * t], w1 = g_tok_w[2 * t + 1];
    float4 a = ((const float4*)(g_y + (size_t)p0 * DD))[j];
    float4 b = ((const float4*)(g_y + (size_t)p1 * DD))[j];
    float4 o;
    o.x = w0 * a.x + w1 * b.x;
    o.y = w0 * a.y + w1 * b.y;
    o.z = w0 * a.z + w1 * b.z;
    o.w = w0 * a.w + w1 * b.w;
    ((float4*)out)[idx] = o;
}

// ---------------------------------------------------------------------------
extern "C" void kernel_launch(void* const* d_in, const int* in_sizes, int n_in,
                              void* d_out, int out_size) {
    const float* z  = (const float*)d_in[0];
    const float* Wg = (const float*)d_in[1];
    const float* bg = (const float*)d_in[2];
    const float* W1 = (const float*)d_in[3];
    const float* b1 = (const float*)d_in[4];
    const float* W2 = (const float*)d_in[5];
    const float* b2 = (const float*)d_in[6];
    float* out = (float*)d_out;

    cudaFuncSetAttribute(moe_gemm<1>, cudaFuncAttributeMaxDynamicSharedMemorySize, SMEMSZ);
    cudaFuncSetAttribute(moe_gemm<2>, cudaFuncAttributeMaxDynamicSharedMemorySize, SMEMSZ);

    init_kernel<<<EE * DD * HH / 4 / 256, 256>>>(W1, W2);             // #0
    gate_kernel<<<BB / 8, 256>>>(z, Wg, bg);                          // #1
    route_kernel<<<1, 256>>>();                                       // #2
    moe_gemm<1><<<dim3(MTILES, HH / BN), 256, SMEMSZ>>>(b1);          // #3 <- ncu
    moe_gemm<2><<<dim3(MTILES, DD / BN), 256, SMEMSZ>>>(b2);          // #4
    combine_kernel<<<BB, 256>>>(out);                                 // #5
}